// round 9
// baseline (speedup 1.0000x reference)
#include <cuda_runtime.h>

#define BB 2
#define SS 2048
#define DIN 1024
#define HH 16
#define DD 64            // DA == DH == 64
#define MTOT (BB*SS)     // 4096

// Scratch (allocation-free rule: __device__ globals)
__device__ float g_Q[BB*HH*SS*DD];    // [b][h][s][d]
__device__ float g_K[BB*HH*SS*DD];
__device__ float g_V[BB*HH*SS*DD];
__device__ float g_ctx[MTOT*HH*DD];   // [b][s][h*64+d]

// ---------------------------------------------------------------------------
// Fused QKV projection: C = X (4096x1024) @ W^T, W in {wq,wk,wv} each (1024x1024)
// scattered into [b][h][s][d] layout. 64x64x16 tiles, 4x4 microtile, 256 thr.
// ---------------------------------------------------------------------------
__global__ __launch_bounds__(256) void qkv_gemm(
    const float* __restrict__ X,
    const float* __restrict__ Wq,
    const float* __restrict__ Wk,
    const float* __restrict__ Wv)
{
    __shared__ float As[16][65];
    __shared__ float Bs[16][65];

    const int nblk = blockIdx.x;            // 0..47
    const int which = nblk >> 4;            // 0=Q,1=K,2=V
    const float* W = (which == 0) ? Wq : (which == 1 ? Wk : Wv);
    float* Dst = (which == 0) ? g_Q : (which == 1 ? g_K : g_V);
    const int n0 = (nblk & 15) * 64;
    const int m0 = blockIdx.y * 64;

    const int tid = threadIdx.x;
    const int tx = tid & 15, ty = tid >> 4;
    const int lrow = tid >> 2;              // 0..63
    const int lk4 = (tid & 3) * 4;          // 0,4,8,12

    float acc[4][4] = {};

    for (int kt = 0; kt < DIN; kt += 16) {
        float4 a = *(const float4*)&X[(m0 + lrow) * DIN + kt + lk4];
        float4 b = *(const float4*)&W[(n0 + lrow) * DIN + kt + lk4];
        As[lk4 + 0][lrow] = a.x; As[lk4 + 1][lrow] = a.y;
        As[lk4 + 2][lrow] = a.z; As[lk4 + 3][lrow] = a.w;
        Bs[lk4 + 0][lrow] = b.x; Bs[lk4 + 1][lrow] = b.y;
        Bs[lk4 + 2][lrow] = b.z; Bs[lk4 + 3][lrow] = b.w;
        __syncthreads();
#pragma unroll
        for (int k = 0; k < 16; k++) {
            float ra[4], rb[4];
#pragma unroll
            for (int i = 0; i < 4; i++) ra[i] = As[k][ty * 4 + i];
#pragma unroll
            for (int j = 0; j < 4; j++) rb[j] = Bs[k][tx * 4 + j];
#pragma unroll
            for (int i = 0; i < 4; i++)
#pragma unroll
                for (int j = 0; j < 4; j++) acc[i][j] += ra[i] * rb[j];
        }
        __syncthreads();
    }

#pragma unroll
    for (int i = 0; i < 4; i++) {
        int m = m0 + ty * 4 + i;
        int b = m >> 11, s = m & (SS - 1);
#pragma unroll
        for (int j = 0; j < 4; j++) {
            int n = n0 + tx * 4 + j;
            int h = n >> 6, d = n & 63;
            Dst[(((b * HH + h) * SS) + s) * DD + d] = acc[i][j];
        }
    }
}

// ---------------------------------------------------------------------------
// Flash attention fp32, causal. One block = one (b,h) and one 64-row Q tile.
// Dynamic smem: Qt[64][65] (Q^T), Kt[64][65] (K^T), Vs[64][64], Ps[64][65] (P^T)
// ---------------------------------------------------------------------------
#define ATTN_SMEM ((64*65 + 64*65 + 64*64 + 64*65) * 4)

__global__ __launch_bounds__(256) void flash_attn()
{
    extern __shared__ float sm[];
    float* Qt = sm;                 // [d][r], pad 65
    float* Kt = Qt + 64 * 65;       // [d][c], pad 65
    float* Vs = Kt + 64 * 65;       // [c][d], width 64
    float* Ps = Vs + 64 * 64;       // [c][r], pad 65

    const int bh = blockIdx.y;      // 0..31
    const int qt = blockIdx.x;      // 0..31
    const float* Qg = g_Q + bh * SS * DD;
    const float* Kg = g_K + bh * SS * DD;
    const float* Vg = g_V + bh * SS * DD;

    const int tid = threadIdx.x;
    const int tx = tid & 15, ty = tid >> 4;
    const int q0 = qt * 64;

    // load Q tile transposed
#pragma unroll
    for (int it = 0; it < 4; it++) {
        int idx = tid + it * 256;         // float4 index 0..1023
        int r = idx >> 4;
        int d0 = (idx & 15) * 4;
        float4 v = *(const float4*)&Qg[(q0 + r) * DD + d0];
        Qt[(d0 + 0) * 65 + r] = v.x;
        Qt[(d0 + 1) * 65 + r] = v.y;
        Qt[(d0 + 2) * 65 + r] = v.z;
        Qt[(d0 + 3) * 65 + r] = v.w;
    }

    float m_i[4], l_i[4], o[4][4];
#pragma unroll
    for (int i = 0; i < 4; i++) {
        m_i[i] = -1e30f; l_i[i] = 0.f;
#pragma unroll
        for (int j = 0; j < 4; j++) o[i][j] = 0.f;
    }

    for (int jt = 0; jt <= qt; jt++) {
        // load K tile (transposed) + V tile
#pragma unroll
        for (int it = 0; it < 4; it++) {
            int idx = tid + it * 256;
            int r = idx >> 4;
            int d0 = (idx & 15) * 4;
            float4 kv = *(const float4*)&Kg[(jt * 64 + r) * DD + d0];
            Kt[(d0 + 0) * 65 + r] = kv.x;
            Kt[(d0 + 1) * 65 + r] = kv.y;
            Kt[(d0 + 2) * 65 + r] = kv.z;
            Kt[(d0 + 3) * 65 + r] = kv.w;
            float4 vv = *(const float4*)&Vg[(jt * 64 + r) * DD + d0];
            *(float4*)&Vs[r * 64 + d0] = vv;
        }
        __syncthreads();

        // S = scale * Q K^T  (4x4 per thread)
        float s[4][4] = {};
#pragma unroll
        for (int k = 0; k < 64; k++) {
            float ra[4], rb[4];
#pragma unroll
            for (int i = 0; i < 4; i++) ra[i] = Qt[k * 65 + ty * 4 + i];
#pragma unroll
            for (int j = 0; j < 4; j++) rb[j] = Kt[k * 65 + tx * 4 + j];
#pragma unroll
            for (int i = 0; i < 4; i++)
#pragma unroll
                for (int j = 0; j < 4; j++) s[i][j] += ra[i] * rb[j];
        }
#pragma unroll
        for (int i = 0; i < 4; i++)
#pragma unroll
            for (int j = 0; j < 4; j++) s[i][j] *= 0.125f;

        if (jt == qt) {  // diagonal tile: mask cols > rows (tile-aligned)
#pragma unroll
            for (int i = 0; i < 4; i++) {
                int r = ty * 4 + i;
#pragma unroll
                for (int j = 0; j < 4; j++) {
                    int c = tx * 4 + j;
                    if (c > r) s[i][j] = -1e30f;
                }
            }
        }

        // online softmax update per row
        float alpha[4];
#pragma unroll
        for (int i = 0; i < 4; i++) {
            float lm = fmaxf(fmaxf(s[i][0], s[i][1]), fmaxf(s[i][2], s[i][3]));
#pragma unroll
            for (int msk = 1; msk < 16; msk <<= 1)
                lm = fmaxf(lm, __shfl_xor_sync(0xffffffffu, lm, msk));
            float mn = fmaxf(m_i[i], lm);
            alpha[i] = __expf(m_i[i] - mn);
            m_i[i] = mn;
            float rs = 0.f;
#pragma unroll
            for (int j = 0; j < 4; j++) {
                float p = __expf(s[i][j] - mn);
                s[i][j] = p;
                rs += p;
            }
#pragma unroll
            for (int msk = 1; msk < 16; msk <<= 1)
                rs += __shfl_xor_sync(0xffffffffu, rs, msk);
            l_i[i] = l_i[i] * alpha[i] + rs;
#pragma unroll
            for (int j = 0; j < 4; j++) o[i][j] *= alpha[i];
        }

        // write P transposed to shared
#pragma unroll
        for (int i = 0; i < 4; i++)
#pragma unroll
            for (int j = 0; j < 4; j++)
                Ps[(tx * 4 + j) * 65 + ty * 4 + i] = s[i][j];
        __syncthreads();

        // O += P V
#pragma unroll
        for (int k = 0; k < 64; k++) {
            float pa[4], vb[4];
#pragma unroll
            for (int i = 0; i < 4; i++) pa[i] = Ps[k * 65 + ty * 4 + i];
#pragma unroll
            for (int j = 0; j < 4; j++) vb[j] = Vs[k * 64 + tx * 4 + j];
#pragma unroll
            for (int i = 0; i < 4; i++)
#pragma unroll
                for (int j = 0; j < 4; j++) o[i][j] += pa[i] * vb[j];
        }
        __syncthreads();
    }

    // finalize + write ctx[b][s][h*64+d]
    const int b = bh >> 4, h = bh & 15;
#pragma unroll
    for (int i = 0; i < 4; i++) {
        float inv = 1.0f / l_i[i];
        int srow = q0 + ty * 4 + i;
#pragma unroll
        for (int j = 0; j < 4; j++) {
            int d = tx * 4 + j;
            g_ctx[(b * SS + srow) * (HH * DD) + h * DD + d] = o[i][j] * inv;
        }
    }
}

// ---------------------------------------------------------------------------
// Output projection: out = ctx (4096x1024) @ Wo^T (1024x1024) + bo
// ---------------------------------------------------------------------------
__global__ __launch_bounds__(256) void out_gemm(
    const float* __restrict__ Wo,
    const float* __restrict__ bo,
    float* __restrict__ out)
{
    __shared__ float As[16][65];
    __shared__ float Bs[16][65];

    const int n0 = blockIdx.x * 64;
    const int m0 = blockIdx.y * 64;
    const int tid = threadIdx.x;
    const int tx = tid & 15, ty = tid >> 4;
    const int lrow = tid >> 2;
    const int lk4 = (tid & 3) * 4;

    float acc[4][4] = {};

    for (int kt = 0; kt < HH * DD; kt += 16) {
        float4 a = *(const float4*)&g_ctx[(m0 + lrow) * (HH * DD) + kt + lk4];
        float4 b = *(const float4*)&Wo[(n0 + lrow) * (HH * DD) + kt + lk4];
        As[lk4 + 0][lrow] = a.x; As[lk4 + 1][lrow] = a.y;
        As[lk4 + 2][lrow] = a.z; As[lk4 + 3][lrow] = a.w;
        Bs[lk4 + 0][lrow] = b.x; Bs[lk4 + 1][lrow] = b.y;
        Bs[lk4 + 2][lrow] = b.z; Bs[lk4 + 3][lrow] = b.w;
        __syncthreads();
#pragma unroll
        for (int k = 0; k < 16; k++) {
            float ra[4], rb[4];
#pragma unroll
            for (int i = 0; i < 4; i++) ra[i] = As[k][ty * 4 + i];
#pragma unroll
            for (int j = 0; j < 4; j++) rb[j] = Bs[k][tx * 4 + j];
#pragma unroll
            for (int i = 0; i < 4; i++)
#pragma unroll
                for (int j = 0; j < 4; j++) acc[i][j] += ra[i] * rb[j];
        }
        __syncthreads();
    }

#pragma unroll
    for (int i = 0; i < 4; i++) {
        int m = m0 + ty * 4 + i;
#pragma unroll
        for (int j = 0; j < 4; j++) {
            int n = n0 + tx * 4 + j;
            out[m * 1024 + n] = acc[i][j] + bo[n];
        }
    }
}

// ---------------------------------------------------------------------------
extern "C" void kernel_launch(void* const* d_in, const int* in_sizes, int n_in,
                              void* d_out, int out_size)
{
    const float* x  = (const float*)d_in[0];
    // d_in[1] = attn_mask (int32 causal tril) — structure is known, ignored
    const float* wq = (const float*)d_in[2];
    const float* wk = (const float*)d_in[3];
    const float* wv = (const float*)d_in[4];
    const float* wo = (const float*)d_in[5];
    const float* bo = (const float*)d_in[6];
    float* out = (float*)d_out;

    cudaFuncSetAttribute(flash_attn,
                         cudaFuncAttributeMaxDynamicSharedMemorySize, ATTN_SMEM);

    qkv_gemm<<<dim3(48, 64), 256>>>(x, wq, wk, wv);
    flash_attn<<<dim3(32, 32), 256, ATTN_SMEM>>>();
    out_gemm<<<dim3(16, 64), 256>>>(wo, bo, out);
}

// round 10
// speedup vs baseline: 1.0161x; 1.0161x over previous
#include <cuda_runtime.h>

#define BB 2
#define SS 2048
#define DIN 1024
#define HH 16
#define DD 64            // DA == DH == 64
#define MTOT (BB*SS)     // 4096

// Scratch (allocation-free rule: __device__ globals)
__device__ float g_Q[BB*HH*SS*DD];    // [b][h][s][d]
__device__ float g_K[BB*HH*SS*DD];
__device__ float g_V[BB*HH*SS*DD];
__device__ float g_ctx[MTOT*HH*DD];   // [b][s][h*64+d]

// ---------------------------------------------------------------------------
// Fused QKV projection: C = X (4096x1024) @ W^T, W in {wq,wk,wv} each (1024x1024)
// scattered into [b][h][s][d] layout. 64x64x16 tiles, 4x4 microtile, 256 thr.
// ---------------------------------------------------------------------------
__global__ __launch_bounds__(256) void qkv_gemm(
    const float* __restrict__ X,
    const float* __restrict__ Wq,
    const float* __restrict__ Wk,
    const float* __restrict__ Wv)
{
    __shared__ float As[16][65];
    __shared__ float Bs[16][65];

    const int nblk = blockIdx.x;            // 0..47
    const int which = nblk >> 4;            // 0=Q,1=K,2=V
    const float* W = (which == 0) ? Wq : (which == 1 ? Wk : Wv);
    float* Dst = (which == 0) ? g_Q : (which == 1 ? g_K : g_V);
    const int n0 = (nblk & 15) * 64;
    const int m0 = blockIdx.y * 64;

    const int tid = threadIdx.x;
    const int tx = tid & 15, ty = tid >> 4;
    const int lrow = tid >> 2;              // 0..63
    const int lk4 = (tid & 3) * 4;          // 0,4,8,12

    float acc[4][4] = {};

    for (int kt = 0; kt < DIN; kt += 16) {
        float4 a = *(const float4*)&X[(m0 + lrow) * DIN + kt + lk4];
        float4 b = *(const float4*)&W[(n0 + lrow) * DIN + kt + lk4];
        As[lk4 + 0][lrow] = a.x; As[lk4 + 1][lrow] = a.y;
        As[lk4 + 2][lrow] = a.z; As[lk4 + 3][lrow] = a.w;
        Bs[lk4 + 0][lrow] = b.x; Bs[lk4 + 1][lrow] = b.y;
        Bs[lk4 + 2][lrow] = b.z; Bs[lk4 + 3][lrow] = b.w;
        __syncthreads();
#pragma unroll
        for (int k = 0; k < 16; k++) {
            float ra[4], rb[4];
#pragma unroll
            for (int i = 0; i < 4; i++) ra[i] = As[k][ty * 4 + i];
#pragma unroll
            for (int j = 0; j < 4; j++) rb[j] = Bs[k][tx * 4 + j];
#pragma unroll
            for (int i = 0; i < 4; i++)
#pragma unroll
                for (int j = 0; j < 4; j++) acc[i][j] += ra[i] * rb[j];
        }
        __syncthreads();
    }

#pragma unroll
    for (int i = 0; i < 4; i++) {
        int m = m0 + ty * 4 + i;
        int b = m >> 11, s = m & (SS - 1);
#pragma unroll
        for (int j = 0; j < 4; j++) {
            int n = n0 + tx * 4 + j;
            int h = n >> 6, d = n & 63;
            Dst[(((b * HH + h) * SS) + s) * DD + d] = acc[i][j];
        }
    }
}

// ---------------------------------------------------------------------------
// Flash attention fp32, causal. One block = one (b,h) and one 64-row Q tile.
// Dynamic smem: Qt[64][65] (Q^T), Kt[64][65] (K^T), Vs[64][64], Ps[64][65] (P^T)
// ---------------------------------------------------------------------------
#define ATTN_SMEM ((64*65 + 64*65 + 64*64 + 64*65) * 4)

__global__ __launch_bounds__(256) void flash_attn()
{
    extern __shared__ float sm[];
    float* Qt = sm;                 // [d][r], pad 65
    float* Kt = Qt + 64 * 65;       // [d][c], pad 65
    float* Vs = Kt + 64 * 65;       // [c][d], width 64
    float* Ps = Vs + 64 * 64;       // [c][r], pad 65

    const int bh = blockIdx.y;      // 0..31
    const int qt = blockIdx.x;      // 0..31
    const float* Qg = g_Q + bh * SS * DD;
    const float* Kg = g_K + bh * SS * DD;
    const float* Vg = g_V + bh * SS * DD;

    const int tid = threadIdx.x;
    const int tx = tid & 15, ty = tid >> 4;
    const int q0 = qt * 64;

    // load Q tile transposed
#pragma unroll
    for (int it = 0; it < 4; it++) {
        int idx = tid + it * 256;         // float4 index 0..1023
        int r = idx >> 4;
        int d0 = (idx & 15) * 4;
        float4 v = *(const float4*)&Qg[(q0 + r) * DD + d0];
        Qt[(d0 + 0) * 65 + r] = v.x;
        Qt[(d0 + 1) * 65 + r] = v.y;
        Qt[(d0 + 2) * 65 + r] = v.z;
        Qt[(d0 + 3) * 65 + r] = v.w;
    }

    float m_i[4], l_i[4], o[4][4];
#pragma unroll
    for (int i = 0; i < 4; i++) {
        m_i[i] = -1e30f; l_i[i] = 0.f;
#pragma unroll
        for (int j = 0; j < 4; j++) o[i][j] = 0.f;
    }

    for (int jt = 0; jt <= qt; jt++) {
        // load K tile (transposed) + V tile
#pragma unroll
        for (int it = 0; it < 4; it++) {
            int idx = tid + it * 256;
            int r = idx >> 4;
            int d0 = (idx & 15) * 4;
            float4 kv = *(const float4*)&Kg[(jt * 64 + r) * DD + d0];
            Kt[(d0 + 0) * 65 + r] = kv.x;
            Kt[(d0 + 1) * 65 + r] = kv.y;
            Kt[(d0 + 2) * 65 + r] = kv.z;
            Kt[(d0 + 3) * 65 + r] = kv.w;
            float4 vv = *(const float4*)&Vg[(jt * 64 + r) * DD + d0];
            *(float4*)&Vs[r * 64 + d0] = vv;
        }
        __syncthreads();

        // S = scale * Q K^T  (4x4 per thread)
        float s[4][4] = {};
#pragma unroll
        for (int k = 0; k < 64; k++) {
            float ra[4], rb[4];
#pragma unroll
            for (int i = 0; i < 4; i++) ra[i] = Qt[k * 65 + ty * 4 + i];
#pragma unroll
            for (int j = 0; j < 4; j++) rb[j] = Kt[k * 65 + tx * 4 + j];
#pragma unroll
            for (int i = 0; i < 4; i++)
#pragma unroll
                for (int j = 0; j < 4; j++) s[i][j] += ra[i] * rb[j];
        }
#pragma unroll
        for (int i = 0; i < 4; i++)
#pragma unroll
            for (int j = 0; j < 4; j++) s[i][j] *= 0.125f;

        if (jt == qt) {  // diagonal tile: mask cols > rows (tile-aligned)
#pragma unroll
            for (int i = 0; i < 4; i++) {
                int r = ty * 4 + i;
#pragma unroll
                for (int j = 0; j < 4; j++) {
                    int c = tx * 4 + j;
                    if (c > r) s[i][j] = -1e30f;
                }
            }
        }

        // online softmax update per row
        float alpha[4];
#pragma unroll
        for (int i = 0; i < 4; i++) {
            float lm = fmaxf(fmaxf(s[i][0], s[i][1]), fmaxf(s[i][2], s[i][3]));
#pragma unroll
            for (int msk = 1; msk < 16; msk <<= 1)
                lm = fmaxf(lm, __shfl_xor_sync(0xffffffffu, lm, msk));
            float mn = fmaxf(m_i[i], lm);
            alpha[i] = __expf(m_i[i] - mn);
            m_i[i] = mn;
            float rs = 0.f;
#pragma unroll
            for (int j = 0; j < 4; j++) {
                float p = __expf(s[i][j] - mn);
                s[i][j] = p;
                rs += p;
            }
#pragma unroll
            for (int msk = 1; msk < 16; msk <<= 1)
                rs += __shfl_xor_sync(0xffffffffu, rs, msk);
            l_i[i] = l_i[i] * alpha[i] + rs;
#pragma unroll
            for (int j = 0; j < 4; j++) o[i][j] *= alpha[i];
        }

        // write P transposed to shared
#pragma unroll
        for (int i = 0; i < 4; i++)
#pragma unroll
            for (int j = 0; j < 4; j++)
                Ps[(tx * 4 + j) * 65 + ty * 4 + i] = s[i][j];
        __syncthreads();

        // O += P V
#pragma unroll
        for (int k = 0; k < 64; k++) {
            float pa[4], vb[4];
#pragma unroll
            for (int i = 0; i < 4; i++) pa[i] = Ps[k * 65 + ty * 4 + i];
#pragma unroll
            for (int j = 0; j < 4; j++) vb[j] = Vs[k * 64 + tx * 4 + j];
#pragma unroll
            for (int i = 0; i < 4; i++)
#pragma unroll
                for (int j = 0; j < 4; j++) o[i][j] += pa[i] * vb[j];
        }
        __syncthreads();
    }

    // finalize + write ctx[b][s][h*64+d]
    const int b = bh >> 4, h = bh & 15;
#pragma unroll
    for (int i = 0; i < 4; i++) {
        float inv = 1.0f / l_i[i];
        int srow = q0 + ty * 4 + i;
#pragma unroll
        for (int j = 0; j < 4; j++) {
            int d = tx * 4 + j;
            g_ctx[(b * SS + srow) * (HH * DD) + h * DD + d] = o[i][j] * inv;
        }
    }
}

// ---------------------------------------------------------------------------
// Output projection: out = ctx (4096x1024) @ Wo^T (1024x1024) + bo
// ---------------------------------------------------------------------------
__global__ __launch_bounds__(256) void out_gemm(
    const float* __restrict__ Wo,
    const float* __restrict__ bo,
    float* __restrict__ out)
{
    __shared__ float As[16][65];
    __shared__ float Bs[16][65];

    const int n0 = blockIdx.x * 64;
    const int m0 = blockIdx.y * 64;
    const int tid = threadIdx.x;
    const int tx = tid & 15, ty = tid >> 4;
    const int lrow = tid >> 2;
    const int lk4 = (tid & 3) * 4;

    float acc[4][4] = {};

    for (int kt = 0; kt < HH * DD; kt += 16) {
        float4 a = *(const float4*)&g_ctx[(m0 + lrow) * (HH * DD) + kt + lk4];
        float4 b = *(const float4*)&Wo[(n0 + lrow) * (HH * DD) + kt + lk4];
        As[lk4 + 0][lrow] = a.x; As[lk4 + 1][lrow] = a.y;
        As[lk4 + 2][lrow] = a.z; As[lk4 + 3][lrow] = a.w;
        Bs[lk4 + 0][lrow] = b.x; Bs[lk4 + 1][lrow] = b.y;
        Bs[lk4 + 2][lrow] = b.z; Bs[lk4 + 3][lrow] = b.w;
        __syncthreads();
#pragma unroll
        for (int k = 0; k < 16; k++) {
            float ra[4], rb[4];
#pragma unroll
            for (int i = 0; i < 4; i++) ra[i] = As[k][ty * 4 + i];
#pragma unroll
            for (int j = 0; j < 4; j++) rb[j] = Bs[k][tx * 4 + j];
#pragma unroll
            for (int i = 0; i < 4; i++)
#pragma unroll
                for (int j = 0; j < 4; j++) acc[i][j] += ra[i] * rb[j];
        }
        __syncthreads();
    }

#pragma unroll
    for (int i = 0; i < 4; i++) {
        int m = m0 + ty * 4 + i;
#pragma unroll
        for (int j = 0; j < 4; j++) {
            int n = n0 + tx * 4 + j;
            out[m * 1024 + n] = acc[i][j] + bo[n];
        }
    }
}

// ---------------------------------------------------------------------------
extern "C" void kernel_launch(void* const* d_in, const int* in_sizes, int n_in,
                              void* d_out, int out_size)
{
    const float* x  = (const float*)d_in[0];
    // d_in[1] = attn_mask (int32 causal tril) — structure is known, ignored
    const float* wq = (const float*)d_in[2];
    const float* wk = (const float*)d_in[3];
    const float* wv = (const float*)d_in[4];
    const float* wo = (const float*)d_in[5];
    const float* bo = (const float*)d_in[6];
    float* out = (float*)d_out;

    cudaFuncSetAttribute(flash_attn,
                         cudaFuncAttributeMaxDynamicSharedMemorySize, ATTN_SMEM);

    qkv_gemm<<<dim3(48, 64), 256>>>(x, wq, wk, wv);
    flash_attn<<<dim3(32, 32), 256, ATTN_SMEM>>>();
    out_gemm<<<dim3(16, 64), 256>>>(wo, bo, out);
}

// round 11
// speedup vs baseline: 1.2632x; 1.2432x over previous
#include <cuda_runtime.h>

#define BB 2
#define SS 2048
#define DIN 1024
#define HH 16
#define DD 64            // DA == DH == 64
#define MTOT (BB*SS)     // 4096
#define BK 16

// Scratch (allocation-free rule: __device__ globals)
__device__ float g_Q[BB*HH*SS*DD];    // [b][h][s][d]
__device__ float g_K[BB*HH*SS*DD];
__device__ float g_V[BB*HH*SS*DD];
__device__ float g_ctx[MTOT*HH*DD];   // [b][s][h*64+d]

// ---------------------------------------------------------------------------
// Fused QKV projection: C = X (4096x1024) @ W^T, W in {wq,wk,wv} each (1024x1024)
// 128x128x16 tiles, 8x8 microtile, 256 threads. Scatter into [b][h][s][d].
// ---------------------------------------------------------------------------
__global__ __launch_bounds__(256) void qkv_gemm(
    const float* __restrict__ X,
    const float* __restrict__ Wq,
    const float* __restrict__ Wk,
    const float* __restrict__ Wv)
{
    __shared__ float As[BK][132];
    __shared__ float Bs[BK][132];

    const int nblk = blockIdx.x;            // 0..23
    const int which = nblk >> 3;            // 0=Q,1=K,2=V
    const float* W = (which == 0) ? Wq : (which == 1 ? Wk : Wv);
    float* Dst = (which == 0) ? g_Q : (which == 1 ? g_K : g_V);
    const int n0 = (nblk & 7) * 128;
    const int m0 = blockIdx.y * 128;

    const int tid = threadIdx.x;
    const int tx = tid & 15, ty = tid >> 4;
    const int lrow = tid >> 2;              // 0..63
    const int lk = (tid & 3) * 4;           // 0,4,8,12

    float acc[8][8] = {};

    for (int kt = 0; kt < DIN; kt += BK) {
#pragma unroll
        for (int it = 0; it < 2; it++) {
            int row = lrow + it * 64;
            float4 a = *(const float4*)&X[(m0 + row) * DIN + kt + lk];
            As[lk + 0][row] = a.x; As[lk + 1][row] = a.y;
            As[lk + 2][row] = a.z; As[lk + 3][row] = a.w;
            float4 b = *(const float4*)&W[(n0 + row) * DIN + kt + lk];
            Bs[lk + 0][row] = b.x; Bs[lk + 1][row] = b.y;
            Bs[lk + 2][row] = b.z; Bs[lk + 3][row] = b.w;
        }
        __syncthreads();
#pragma unroll
        for (int k = 0; k < BK; k++) {
            float ra[8], rb[8];
            *(float4*)&ra[0] = *(const float4*)&As[k][ty * 8];
            *(float4*)&ra[4] = *(const float4*)&As[k][ty * 8 + 4];
            *(float4*)&rb[0] = *(const float4*)&Bs[k][tx * 8];
            *(float4*)&rb[4] = *(const float4*)&Bs[k][tx * 8 + 4];
#pragma unroll
            for (int i = 0; i < 8; i++)
#pragma unroll
                for (int j = 0; j < 8; j++) acc[i][j] += ra[i] * rb[j];
        }
        __syncthreads();
    }

    // epilogue: n0+tx*8 is 8-aligned, so 8 consecutive n share one head h
    const int nb = n0 + tx * 8;
    const int h = nb >> 6, d = nb & 63;
#pragma unroll
    for (int i = 0; i < 8; i++) {
        int m = m0 + ty * 8 + i;
        int b = m >> 11, s = m & (SS - 1);
        float* dst = &Dst[(((b * HH + h) * SS) + s) * DD + d];
        *(float4*)&dst[0] = make_float4(acc[i][0], acc[i][1], acc[i][2], acc[i][3]);
        *(float4*)&dst[4] = make_float4(acc[i][4], acc[i][5], acc[i][6], acc[i][7]);
    }
}

// ---------------------------------------------------------------------------
// Flash attention fp32, causal. One block = one (b,h) and one 64-row Q tile.
// Dynamic smem: Qt[64][65] (Q^T), Kt[64][65] (K^T), Vs[64][64], Ps[64][65] (P^T)
// ---------------------------------------------------------------------------
#define ATTN_SMEM ((64*65 + 64*65 + 64*64 + 64*65) * 4)

__global__ __launch_bounds__(256) void flash_attn()
{
    extern __shared__ float sm[];
    float* Qt = sm;                 // [d][r], pad 65
    float* Kt = Qt + 64 * 65;       // [d][c], pad 65
    float* Vs = Kt + 64 * 65;       // [c][d], width 64
    float* Ps = Vs + 64 * 64;       // [c][r], pad 65

    const int bh = blockIdx.y;      // 0..31
    const int qt = 31 - blockIdx.x; // longest-job-first scheduling
    const float* Qg = g_Q + bh * SS * DD;
    const float* Kg = g_K + bh * SS * DD;
    const float* Vg = g_V + bh * SS * DD;

    const int tid = threadIdx.x;
    const int tx = tid & 15, ty = tid >> 4;
    const int q0 = qt * 64;

    // load Q tile transposed
#pragma unroll
    for (int it = 0; it < 4; it++) {
        int idx = tid + it * 256;         // float4 index 0..1023
        int r = idx >> 4;
        int d0 = (idx & 15) * 4;
        float4 v = *(const float4*)&Qg[(q0 + r) * DD + d0];
        Qt[(d0 + 0) * 65 + r] = v.x;
        Qt[(d0 + 1) * 65 + r] = v.y;
        Qt[(d0 + 2) * 65 + r] = v.z;
        Qt[(d0 + 3) * 65 + r] = v.w;
    }

    float m_i[4], l_i[4], o[4][4];
#pragma unroll
    for (int i = 0; i < 4; i++) {
        m_i[i] = -1e30f; l_i[i] = 0.f;
#pragma unroll
        for (int j = 0; j < 4; j++) o[i][j] = 0.f;
    }

    for (int jt = 0; jt <= qt; jt++) {
        // load K tile (transposed) + V tile
#pragma unroll
        for (int it = 0; it < 4; it++) {
            int idx = tid + it * 256;
            int r = idx >> 4;
            int d0 = (idx & 15) * 4;
            float4 kv = *(const float4*)&Kg[(jt * 64 + r) * DD + d0];
            Kt[(d0 + 0) * 65 + r] = kv.x;
            Kt[(d0 + 1) * 65 + r] = kv.y;
            Kt[(d0 + 2) * 65 + r] = kv.z;
            Kt[(d0 + 3) * 65 + r] = kv.w;
            float4 vv = *(const float4*)&Vg[(jt * 64 + r) * DD + d0];
            *(float4*)&Vs[r * 64 + d0] = vv;
        }
        __syncthreads();

        // S = scale * Q K^T  (4x4 per thread)
        float s[4][4] = {};
#pragma unroll
        for (int k = 0; k < 64; k++) {
            float ra[4], rb[4];
#pragma unroll
            for (int i = 0; i < 4; i++) ra[i] = Qt[k * 65 + ty * 4 + i];
#pragma unroll
            for (int j = 0; j < 4; j++) rb[j] = Kt[k * 65 + tx * 4 + j];
#pragma unroll
            for (int i = 0; i < 4; i++)
#pragma unroll
                for (int j = 0; j < 4; j++) s[i][j] += ra[i] * rb[j];
        }
#pragma unroll
        for (int i = 0; i < 4; i++)
#pragma unroll
            for (int j = 0; j < 4; j++) s[i][j] *= 0.125f;

        if (jt == qt) {  // diagonal tile: mask cols > rows (tile-aligned)
#pragma unroll
            for (int i = 0; i < 4; i++) {
                int r = ty * 4 + i;
#pragma unroll
                for (int j = 0; j < 4; j++) {
                    int c = tx * 4 + j;
                    if (c > r) s[i][j] = -1e30f;
                }
            }
        }

        // online softmax update per row
        float alpha[4];
#pragma unroll
        for (int i = 0; i < 4; i++) {
            float lm = fmaxf(fmaxf(s[i][0], s[i][1]), fmaxf(s[i][2], s[i][3]));
#pragma unroll
            for (int msk = 1; msk < 16; msk <<= 1)
                lm = fmaxf(lm, __shfl_xor_sync(0xffffffffu, lm, msk));
            float mn = fmaxf(m_i[i], lm);
            alpha[i] = __expf(m_i[i] - mn);
            m_i[i] = mn;
            float rs = 0.f;
#pragma unroll
            for (int j = 0; j < 4; j++) {
                float p = __expf(s[i][j] - mn);
                s[i][j] = p;
                rs += p;
            }
#pragma unroll
            for (int msk = 1; msk < 16; msk <<= 1)
                rs += __shfl_xor_sync(0xffffffffu, rs, msk);
            l_i[i] = l_i[i] * alpha[i] + rs;
#pragma unroll
            for (int j = 0; j < 4; j++) o[i][j] *= alpha[i];
        }

        // write P transposed to shared
#pragma unroll
        for (int i = 0; i < 4; i++)
#pragma unroll
            for (int j = 0; j < 4; j++)
                Ps[(tx * 4 + j) * 65 + ty * 4 + i] = s[i][j];
        __syncthreads();

        // O += P V
#pragma unroll
        for (int k = 0; k < 64; k++) {
            float pa[4], vb[4];
#pragma unroll
            for (int i = 0; i < 4; i++) pa[i] = Ps[k * 65 + ty * 4 + i];
#pragma unroll
            for (int j = 0; j < 4; j++) vb[j] = Vs[k * 64 + tx * 4 + j];
#pragma unroll
            for (int i = 0; i < 4; i++)
#pragma unroll
                for (int j = 0; j < 4; j++) o[i][j] += pa[i] * vb[j];
        }
        __syncthreads();
    }

    // finalize + write ctx[b][s][h*64+d]
    const int b = bh >> 4, h = bh & 15;
#pragma unroll
    for (int i = 0; i < 4; i++) {
        float inv = 1.0f / l_i[i];
        int srow = q0 + ty * 4 + i;
#pragma unroll
        for (int j = 0; j < 4; j++) {
            int d = tx * 4 + j;
            g_ctx[(b * SS + srow) * (HH * DD) + h * DD + d] = o[i][j] * inv;
        }
    }
}

// ---------------------------------------------------------------------------
// Output projection: out = ctx (4096x1024) @ Wo^T (1024x1024) + bo
// 128x128x16 tiles, 8x8 microtile, 256 threads.
// ---------------------------------------------------------------------------
__global__ __launch_bounds__(256) void out_gemm(
    const float* __restrict__ Wo,
    const float* __restrict__ bo,
    float* __restrict__ out)
{
    __shared__ float As[BK][132];
    __shared__ float Bs[BK][132];

    const int n0 = blockIdx.x * 128;
    const int m0 = blockIdx.y * 128;
    const int tid = threadIdx.x;
    const int tx = tid & 15, ty = tid >> 4;
    const int lrow = tid >> 2;
    const int lk = (tid & 3) * 4;

    float acc[8][8] = {};

    for (int kt = 0; kt < HH * DD; kt += BK) {
#pragma unroll
        for (int it = 0; it < 2; it++) {
            int row = lrow + it * 64;
            float4 a = *(const float4*)&g_ctx[(m0 + row) * (HH * DD) + kt + lk];
            As[lk + 0][row] = a.x; As[lk + 1][row] = a.y;
            As[lk + 2][row] = a.z; As[lk + 3][row] = a.w;
            float4 b = *(const float4*)&Wo[(n0 + row) * (HH * DD) + kt + lk];
            Bs[lk + 0][row] = b.x; Bs[lk + 1][row] = b.y;
            Bs[lk + 2][row] = b.z; Bs[lk + 3][row] = b.w;
        }
        __syncthreads();
#pragma unroll
        for (int k = 0; k < BK; k++) {
            float ra[8], rb[8];
            *(float4*)&ra[0] = *(const float4*)&As[k][ty * 8];
            *(float4*)&ra[4] = *(const float4*)&As[k][ty * 8 + 4];
            *(float4*)&rb[0] = *(const float4*)&Bs[k][tx * 8];
            *(float4*)&rb[4] = *(const float4*)&Bs[k][tx * 8 + 4];
#pragma unroll
            for (int i = 0; i < 8; i++)
#pragma unroll
                for (int j = 0; j < 8; j++) acc[i][j] += ra[i] * rb[j];
        }
        __syncthreads();
    }

    float bias[8];
    *(float4*)&bias[0] = *(const float4*)&bo[n0 + tx * 8];
    *(float4*)&bias[4] = *(const float4*)&bo[n0 + tx * 8 + 4];

#pragma unroll
    for (int i = 0; i < 8; i++) {
        int m = m0 + ty * 8 + i;
        float* dst = &out[m * 1024 + n0 + tx * 8];
        *(float4*)&dst[0] = make_float4(acc[i][0] + bias[0], acc[i][1] + bias[1],
                                        acc[i][2] + bias[2], acc[i][3] + bias[3]);
        *(float4*)&dst[4] = make_float4(acc[i][4] + bias[4], acc[i][5] + bias[5],
                                        acc[i][6] + bias[6], acc[i][7] + bias[7]);
    }
}

// ---------------------------------------------------------------------------
extern "C" void kernel_launch(void* const* d_in, const int* in_sizes, int n_in,
                              void* d_out, int out_size)
{
    const float* x  = (const float*)d_in[0];
    // d_in[1] = attn_mask (int32 causal tril) — structure is known, ignored
    const float* wq = (const float*)d_in[2];
    const float* wk = (const float*)d_in[3];
    const float* wv = (const float*)d_in[4];
    const float* wo = (const float*)d_in[5];
    const float* bo = (const float*)d_in[6];
    float* out = (float*)d_out;

    cudaFuncSetAttribute(flash_attn,
                         cudaFuncAttributeMaxDynamicSharedMemorySize, ATTN_SMEM);

    qkv_gemm<<<dim3(24, 32), 256>>>(x, wq, wk, wv);
    flash_attn<<<dim3(32, 32), 256, ATTN_SMEM>>>();
    out_gemm<<<dim3(8, 32), 256>>>(wo, bo, out);
}

// round 12
// speedup vs baseline: 2.0445x; 1.6184x over previous
#include <cuda_runtime.h>

#define BB 2
#define SS 2048
#define DIN 1024
#define HH 16
#define DD 64
#define MTOT (BB*SS)

// Scratch (allocation-free rule: __device__ globals)
__device__ float g_Q[BB*HH*SS*DD];    // [b][h][s][d]
__device__ float g_K[BB*HH*SS*DD];
__device__ float g_V[BB*HH*SS*DD];
__device__ float g_ctx[MTOT*HH*DD];   // [b][s][h*64+d]

// ---------------------------------------------------------------------------
// TF32 helpers
// ---------------------------------------------------------------------------
__device__ __forceinline__ unsigned f2tf(float f) {
    unsigned r;
    asm("cvt.rna.tf32.f32 %0, %1;" : "=r"(r) : "f"(f));
    return r;
}

__device__ __forceinline__ void mma_tf32(float c[4],
    unsigned a0, unsigned a1, unsigned a2, unsigned a3,
    unsigned b0, unsigned b1)
{
    asm volatile(
        "mma.sync.aligned.m16n8k8.row.col.f32.tf32.tf32.f32 "
        "{%0,%1,%2,%3}, {%4,%5,%6,%7}, {%8,%9}, {%0,%1,%2,%3};"
        : "+f"(c[0]), "+f"(c[1]), "+f"(c[2]), "+f"(c[3])
        : "r"(a0), "r"(a1), "r"(a2), "r"(a3), "r"(b0), "r"(b1));
}

// Shared mainloop: acc += A(m0:+128, :) @ B(n0:+128, :)^T, K=1024, tf32.
// As/Bs layout [row][36] (pad 4): STS.128 staging conflict-free, fragment
// LDS bank = (4*row + k) % 32 conflict-free.
__device__ __forceinline__ void tf32_mainloop(
    const float* __restrict__ Ag, const float* __restrict__ Bg,
    int m0, int n0, int tid,
    unsigned (*As)[36], unsigned (*Bs)[36],
    float acc[4][4][4])
{
    const int lane = tid & 31, wid = tid >> 5;
    const int wm = wid >> 2, wn = wid & 3;      // warp 64x32 region
    const int g = lane >> 2, t = lane & 3;
    const int srow = tid >> 3;                  // 0..31
    const int skq = (tid & 7) * 4;              // 0..28

    for (int kt = 0; kt < DIN; kt += 32) {
#pragma unroll
        for (int it = 0; it < 4; it++) {
            int row = srow + it * 32;
            float4 a = *(const float4*)&Ag[(m0 + row) * DIN + kt + skq];
            float4 b = *(const float4*)&Bg[(n0 + row) * DIN + kt + skq];
            *(uint4*)&As[row][skq] = make_uint4(f2tf(a.x), f2tf(a.y), f2tf(a.z), f2tf(a.w));
            *(uint4*)&Bs[row][skq] = make_uint4(f2tf(b.x), f2tf(b.y), f2tf(b.z), f2tf(b.w));
        }
        __syncthreads();
#pragma unroll
        for (int ks = 0; ks < 4; ks++) {
            const int k0 = ks * 8;
            unsigned af[4][4], bf[4][2];
#pragma unroll
            for (int mt = 0; mt < 4; mt++) {
                int mr = wm * 64 + mt * 16 + g;
                af[mt][0] = As[mr][k0 + t];
                af[mt][1] = As[mr + 8][k0 + t];
                af[mt][2] = As[mr][k0 + t + 4];
                af[mt][3] = As[mr + 8][k0 + t + 4];
            }
#pragma unroll
            for (int nt = 0; nt < 4; nt++) {
                int nc = wn * 32 + nt * 8 + g;
                bf[nt][0] = Bs[nc][k0 + t];
                bf[nt][1] = Bs[nc][k0 + t + 4];
            }
#pragma unroll
            for (int mt = 0; mt < 4; mt++)
#pragma unroll
                for (int nt = 0; nt < 4; nt++)
                    mma_tf32(acc[mt][nt], af[mt][0], af[mt][1], af[mt][2], af[mt][3],
                             bf[nt][0], bf[nt][1]);
        }
        __syncthreads();
    }
}

// ---------------------------------------------------------------------------
// QKV projection (TF32 tensor cores), scatter into [b][h][s][d]
// ---------------------------------------------------------------------------
__global__ __launch_bounds__(256) void qkv_gemm(
    const float* __restrict__ X,
    const float* __restrict__ Wq,
    const float* __restrict__ Wk,
    const float* __restrict__ Wv)
{
    __shared__ unsigned As[128][36];
    __shared__ unsigned Bs[128][36];

    const int nblk = blockIdx.x;
    const int which = nblk >> 3;
    const float* W = (which == 0) ? Wq : (which == 1 ? Wk : Wv);
    float* Dst = (which == 0) ? g_Q : (which == 1 ? g_K : g_V);
    const int n0 = (nblk & 7) * 128;
    const int m0 = blockIdx.y * 128;

    const int tid = threadIdx.x;
    const int lane = tid & 31, wid = tid >> 5;
    const int wm = wid >> 2, wn = wid & 3;
    const int g = lane >> 2, t = lane & 3;

    float acc[4][4][4] = {};
    tf32_mainloop(X, W, m0, n0, tid, As, Bs, acc);

#pragma unroll
    for (int mt = 0; mt < 4; mt++) {
        int m = m0 + wm * 64 + mt * 16 + g;
        int b = m >> 11, s = m & (SS - 1);
#pragma unroll
        for (int nt = 0; nt < 4; nt++) {
            int n = n0 + wn * 32 + nt * 8 + 2 * t;
            int h = n >> 6, d = n & 63;
            float* dst = &Dst[(((b * HH + h) * SS) + s) * DD + d];
            *(float2*)dst = make_float2(acc[mt][nt][0], acc[mt][nt][1]);
            *(float2*)(dst + 8 * DD) = make_float2(acc[mt][nt][2], acc[mt][nt][3]);
        }
    }
}

// ---------------------------------------------------------------------------
// Output projection (TF32): out = ctx @ Wo^T + bo
// ---------------------------------------------------------------------------
__global__ __launch_bounds__(256) void out_gemm(
    const float* __restrict__ Wo,
    const float* __restrict__ bo,
    float* __restrict__ out)
{
    __shared__ unsigned As[128][36];
    __shared__ unsigned Bs[128][36];

    const int n0 = blockIdx.x * 128;
    const int m0 = blockIdx.y * 128;

    const int tid = threadIdx.x;
    const int lane = tid & 31, wid = tid >> 5;
    const int wm = wid >> 2, wn = wid & 3;
    const int g = lane >> 2, t = lane & 3;

    float acc[4][4][4] = {};
    tf32_mainloop(g_ctx, Wo, m0, n0, tid, As, Bs, acc);

#pragma unroll
    for (int nt = 0; nt < 4; nt++) {
        int n = n0 + wn * 32 + nt * 8 + 2 * t;
        float2 bias = *(const float2*)&bo[n];
#pragma unroll
        for (int mt = 0; mt < 4; mt++) {
            int m = m0 + wm * 64 + mt * 16 + g;
            *(float2*)&out[m * 1024 + n] =
                make_float2(acc[mt][nt][0] + bias.x, acc[mt][nt][1] + bias.y);
            *(float2*)&out[(m + 8) * 1024 + n] =
                make_float2(acc[mt][nt][2] + bias.x, acc[mt][nt][3] + bias.y);
        }
    }
}

// ---------------------------------------------------------------------------
// Flash attention fp32, causal (unchanged from R11).
// ---------------------------------------------------------------------------
#define ATTN_SMEM ((64*65 + 64*65 + 64*64 + 64*65) * 4)

__global__ __launch_bounds__(256) void flash_attn()
{
    extern __shared__ float sm[];
    float* Qt = sm;
    float* Kt = Qt + 64 * 65;
    float* Vs = Kt + 64 * 65;
    float* Ps = Vs + 64 * 64;

    const int bh = blockIdx.y;
    const int qt = 31 - blockIdx.x;   // longest-job-first
    const float* Qg = g_Q + bh * SS * DD;
    const float* Kg = g_K + bh * SS * DD;
    const float* Vg = g_V + bh * SS * DD;

    const int tid = threadIdx.x;
    const int tx = tid & 15, ty = tid >> 4;
    const int q0 = qt * 64;

#pragma unroll
    for (int it = 0; it < 4; it++) {
        int idx = tid + it * 256;
        int r = idx >> 4;
        int d0 = (idx & 15) * 4;
        float4 v = *(const float4*)&Qg[(q0 + r) * DD + d0];
        Qt[(d0 + 0) * 65 + r] = v.x;
        Qt[(d0 + 1) * 65 + r] = v.y;
        Qt[(d0 + 2) * 65 + r] = v.z;
        Qt[(d0 + 3) * 65 + r] = v.w;
    }

    float m_i[4], l_i[4], o[4][4];
#pragma unroll
    for (int i = 0; i < 4; i++) {
        m_i[i] = -1e30f; l_i[i] = 0.f;
#pragma unroll
        for (int j = 0; j < 4; j++) o[i][j] = 0.f;
    }

    for (int jt = 0; jt <= qt; jt++) {
#pragma unroll
        for (int it = 0; it < 4; it++) {
            int idx = tid + it * 256;
            int r = idx >> 4;
            int d0 = (idx & 15) * 4;
            float4 kv = *(const float4*)&Kg[(jt * 64 + r) * DD + d0];
            Kt[(d0 + 0) * 65 + r] = kv.x;
            Kt[(d0 + 1) * 65 + r] = kv.y;
            Kt[(d0 + 2) * 65 + r] = kv.z;
            Kt[(d0 + 3) * 65 + r] = kv.w;
            float4 vv = *(const float4*)&Vg[(jt * 64 + r) * DD + d0];
            *(float4*)&Vs[r * 64 + d0] = vv;
        }
        __syncthreads();

        float s[4][4] = {};
#pragma unroll
        for (int k = 0; k < 64; k++) {
            float ra[4], rb[4];
#pragma unroll
            for (int i = 0; i < 4; i++) ra[i] = Qt[k * 65 + ty * 4 + i];
#pragma unroll
            for (int j = 0; j < 4; j++) rb[j] = Kt[k * 65 + tx * 4 + j];
#pragma unroll
            for (int i = 0; i < 4; i++)
#pragma unroll
                for (int j = 0; j < 4; j++) s[i][j] += ra[i] * rb[j];
        }
#pragma unroll
        for (int i = 0; i < 4; i++)
#pragma unroll
            for (int j = 0; j < 4; j++) s[i][j] *= 0.125f;

        if (jt == qt) {
#pragma unroll
            for (int i = 0; i < 4; i++) {
                int r = ty * 4 + i;
#pragma unroll
                for (int j = 0; j < 4; j++) {
                    int c = tx * 4 + j;
                    if (c > r) s[i][j] = -1e30f;
                }
            }
        }

        float alpha[4];
#pragma unroll
        for (int i = 0; i < 4; i++) {
            float lm = fmaxf(fmaxf(s[i][0], s[i][1]), fmaxf(s[i][2], s[i][3]));
#pragma unroll
            for (int msk = 1; msk < 16; msk <<= 1)
                lm = fmaxf(lm, __shfl_xor_sync(0xffffffffu, lm, msk));
            float mn = fmaxf(m_i[i], lm);
            alpha[i] = __expf(m_i[i] - mn);
            m_i[i] = mn;
            float rs = 0.f;
#pragma unroll
            for (int j = 0; j < 4; j++) {
                float p = __expf(s[i][j] - mn);
                s[i][j] = p;
                rs += p;
            }
#pragma unroll
            for (int msk = 1; msk < 16; msk <<= 1)
                rs += __shfl_xor_sync(0xffffffffu, rs, msk);
            l_i[i] = l_i[i] * alpha[i] + rs;
#pragma unroll
            for (int j = 0; j < 4; j++) o[i][j] *= alpha[i];
        }

#pragma unroll
        for (int i = 0; i < 4; i++)
#pragma unroll
            for (int j = 0; j < 4; j++)
                Ps[(tx * 4 + j) * 65 + ty * 4 + i] = s[i][j];
        __syncthreads();

#pragma unroll
        for (int k = 0; k < 64; k++) {
            float pa[4], vb[4];
#pragma unroll
            for (int i = 0; i < 4; i++) pa[i] = Ps[k * 65 + ty * 4 + i];
#pragma unroll
            for (int j = 0; j < 4; j++) vb[j] = Vs[k * 64 + tx * 4 + j];
#pragma unroll
            for (int i = 0; i < 4; i++)
#pragma unroll
                for (int j = 0; j < 4; j++) o[i][j] += pa[i] * vb[j];
        }
        __syncthreads();
    }

    const int b = bh >> 4, h = bh & 15;
#pragma unroll
    for (int i = 0; i < 4; i++) {
        float inv = 1.0f / l_i[i];
        int srow = q0 + ty * 4 + i;
#pragma unroll
        for (int j = 0; j < 4; j++) {
            int d = tx * 4 + j;
            g_ctx[(b * SS + srow) * (HH * DD) + h * DD + d] = o[i][j] * inv;
        }
    }
}

// ---------------------------------------------------------------------------
extern "C" void kernel_launch(void* const* d_in, const int* in_sizes, int n_in,
                              void* d_out, int out_size)
{
    const float* x  = (const float*)d_in[0];
    const float* wq = (const float*)d_in[2];
    const float* wk = (const float*)d_in[3];
    const float* wv = (const float*)d_in[4];
    const float* wo = (const float*)d_in[5];
    const float* bo = (const float*)d_in[6];
    float* out = (float*)d_out;

    cudaFuncSetAttribute(flash_attn,
                         cudaFuncAttributeMaxDynamicSharedMemorySize, ATTN_SMEM);

    qkv_gemm<<<dim3(24, 32), 256>>>(x, wq, wk, wv);
    flash_attn<<<dim3(32, 32), 256, ATTN_SMEM>>>();
    out_gemm<<<dim3(8, 32), 256>>>(wo, bo, out);
}